// round 10
// baseline (speedup 1.0000x reference)
#include <cuda_runtime.h>
#include <math.h>

#define N_ 128
#define T_ 1024
#define C_ 256
#define L_ 128
#define NEGH (-(1 << 26))
#define RINGD 32             // ring depth in rows (32 x 1KB = 32KB smem)

__device__ float g_loss[N_];
__device__ int   g_ctr;      // cross-CTA completion counter (self-resetting)

// ---------------------------------------------------------------------------
// One 1024-thread CTA per sample.  preds read ONCE.
//  24 producer warps (SMSP0-2), software-pipelined: prefetch row t+24 ->
//    exp2f x8 -> STS exp'd row -> red.release chunk counter -> row-sum via
//    shfl butterfly -> exact product-exponent accumulation (one log at end).
//  warp 31 (alone on SMSP3): CTC DP, 8 states/lane in registers.  Per step:
//    5 LDS (2-step-ahead staging) + ~22 FLOPs; the cross-lane SHFL of the new
//    m7 issues at END of step (hidden), consumed next step.  One acquire-poll
//    per 8 steps; consumed-row watermark published per 8 steps.
//  Last CTA reduces g_loss -> out[0].
// ---------------------------------------------------------------------------
__global__ void __launch_bounds__(1024, 1) ctc_all(const float* __restrict__ preds,
                                                   const int*   __restrict__ targets,
                                                   float*       __restrict__ out) {
    const int n    = blockIdx.x;
    const int tid  = threadIdx.x;
    const int wid  = tid >> 5;
    const int lane = tid & 31;

    __shared__ __align__(16) float ring[RINGD * C_];
    __shared__ int   cnt[T_ / 8];
    __shared__ int   stg[L_];
    __shared__ float wsum[32];
    __shared__ float finm[260];
    __shared__ int   fine_[32];
    __shared__ volatile int s_prog;

    const float* P = preds + (size_t)n * T_ * C_;
    const float L2E = 1.4426950408889634f;

    if (tid < L_) stg[tid] = targets[n * L_ + tid];
    if (tid < T_ / 8) cnt[tid] = 0;
    if (tid < 32) wsum[tid] = 0.0f;
    if (tid == 0) s_prog = -8;
    __syncthreads();

    const unsigned cntb = (unsigned)__cvta_generic_to_shared(cnt);

    if (wid == 31) {
        // =================== DP warp ===================
        const int lab0 = stg[4*lane],   lab1 = stg[4*lane+1];
        const int lab2 = stg[4*lane+2], lab3 = stg[4*lane+3];
        const float sk1 = (lane == 0) ? 1.0f : ((lab0 != stg[4*lane-1]) ? 1.0f : 0.0f);
        const float sk3 = (lab1 != lab0) ? 1.0f : 0.0f;
        const float sk5 = (lab2 != lab1) ? 1.0f : 0.0f;
        const float sk7 = (lab3 != lab2) ? 1.0f : 0.0f;

        #define WAITCNT(K)                                                     \
        {   int cc_; unsigned ca_ = cntb + 4u * (unsigned)(K);                 \
            do { asm volatile("ld.acquire.cta.shared::cta.b32 %0, [%1];"       \
                              : "=r"(cc_) : "r"(ca_) : "memory");              \
            } while (cc_ < 8); }

        float m0=0,m1=0,m2=0,m3=0,m4=0,m5=0,m6=0,m7=0,m8=0;
        float m7n = 0.0f;                       // shfl'd m7 of lane-1 (prev step)
        int   el = 0;
        WAITCNT(0)                              // rows 0..7 resident
        if (lane == 0) { m0 = ring[0]; m1 = ring[lab0]; }   // alpha at t=0
        float fA = (lane == 0) ? 0.0f : 1.0f, fB = 1.0f;

        // 2-deep emission staging: e = row1, n = row2; ci -> row3
        float eB = ring[256],        e0 = ring[256 + lab0];
        float e1 = ring[256 + lab1], e2 = ring[256 + lab2], e3 = ring[256 + lab3];
        float nB = ring[512],        n0 = ring[512 + lab0];
        float n1 = ring[512 + lab1], n2 = ring[512 + lab2], n3 = ring[512 + lab3];
        int ci = 768;

        #define STEPD(DO_STAGE)                                                \
        {                                                                      \
            float lB=0,l0=0,l1=0,l2=0,l3=0;                                    \
            if (DO_STAGE) {                                                    \
                lB = ring[ci];        l0 = ring[ci + lab0];                    \
                l1 = ring[ci + lab1]; l2 = ring[ci + lab2];                    \
                l3 = ring[ci + lab3];                                          \
                ci = (ci + 256) & (RINGD * 256 - 1);                           \
            }                                                                  \
            float in1 = (m7n * fA) * fB;                                       \
            m8 = (m8 + m7) * eB;                                               \
            m7 = fmaf(sk7, m5, m7 + m6) * e3;                                  \
            m6 = (m6 + m5) * eB;                                               \
            m5 = fmaf(sk5, m3, m5 + m4) * e2;                                  \
            m4 = (m4 + m3) * eB;                                               \
            m3 = fmaf(sk3, m1, m3 + m2) * e1;                                  \
            m2 = (m2 + m1) * eB;                                               \
            m1 = fmaf(sk1, in1, m1 + m0) * e0;                                 \
            m0 = (m0 + in1) * eB;                                              \
            m7n = __shfl_up_sync(0xffffffffu, m7, 1);   /* for next step */    \
            eB = nB; e0 = n0; e1 = n1; e2 = n2; e3 = n3;                       \
            nB = lB; n0 = l0; n1 = l1; n2 = l2; n3 = l3;                       \
        }

        #define RENORM                                                         \
        {                                                                      \
            float lm = fmaxf(fmaxf(fmaxf(m0,m1),fmaxf(m2,m3)),                 \
                             fmaxf(fmaxf(m4,m5),fmaxf(m6,m7)));                \
            lm = fmaxf(lm, m8);                                                \
            int bts = __float_as_int(lm);                                      \
            int x   = ((bts >> 23) & 255) - 127;                               \
            int elo = (lm > 0.0f) ? (el + x) : NEGH;                           \
            int eln = __shfl_up_sync(0xffffffffu, elo, 1);                     \
            if (lane == 0) eln = NEGH;                                         \
            int elf = max(elo, eln - 40);                                      \
            int elnf = __shfl_up_sync(0xffffffffu, elf, 1);                    \
            if (lane == 0) elnf = NEGH;                                        \
            int jmp = elf - el;                                                \
            int jc  = min(max(127 - jmp, 0), 254);                             \
            float sc = __int_as_float(jc << 23);                               \
            m0*=sc; m1*=sc; m2*=sc; m3*=sc; m4*=sc;                            \
            m5*=sc; m6*=sc; m7*=sc; m8*=sc;                                    \
            el = elf;                                                          \
            int d  = min(elnf - elf, 40);                                      \
            int h1 = d >> 1;                                                   \
            int h2 = d - h1;                                                   \
            fA = __int_as_float(max(h1 + 127, 0) << 23);                       \
            fB = __int_as_float(max(h2 + 127, 0) << 23);                       \
            if (lane == 0) fA = 0.0f;                                          \
            m7n = __shfl_up_sync(0xffffffffu, m7, 1);   /* rescaled re-shfl */ \
        }

        // blocks j=0..126: steps 8j+1 .. 8j+8 (stage rows up to 8j+10)
        for (int j = 0; j < 127; j++) {
            WAITCNT(j + 1)                      // rows <= 8j+15 resident
            STEPD(1) STEPD(1) STEPD(1) STEPD(1)
            STEPD(1) STEPD(1) STEPD(1) STEPD(1)
            RENORM
            if (lane == 0) s_prog = 8 * j + 8;
        }
        // tail: steps 1017..1023 (rows <=1023 resident after WAITCNT(127))
        STEPD(1) STEPD(1) STEPD(1) STEPD(1) STEPD(1) STEPD(0) STEPD(0)
        #undef STEPD
        #undef RENORM
        #undef WAITCNT

        finm[8*lane+0]=m0; finm[8*lane+1]=m1; finm[8*lane+2]=m2; finm[8*lane+3]=m3;
        finm[8*lane+4]=m4; finm[8*lane+5]=m5; finm[8*lane+6]=m6; finm[8*lane+7]=m7;
        if (lane == 31) finm[256] = m8;
        fine_[lane] = el;
    } else if ((wid & 3) != 3) {
        // =================== producer warps (24), software-pipelined =======
        const int widx = (wid >> 2) * 3 + (wid & 3);   // 0..23
        float prod = 1.0f;                              // product mantissa
        int   eacc = 0;                                 // product exponent
        int   t = widx;
        const float4* row = reinterpret_cast<const float4*>(P + (size_t)t * C_);
        float4 a = row[lane];
        float4 b = row[lane + 32];
        for (; t < T_; t += 24) {
            const int tn = t + 24;
            float4 an, bn;
            if (tn < T_) {                              // prefetch next row now
                const float4* rn = reinterpret_cast<const float4*>(P + (size_t)tn * C_);
                an = rn[lane];
                bn = rn[lane + 32];
            }
            while (t - s_prog > 32) __nanosleep(64);    // ring back-pressure
            float4 ea, eb;
            ea.x = exp2f(a.x*L2E); ea.y = exp2f(a.y*L2E);
            ea.z = exp2f(a.z*L2E); ea.w = exp2f(a.w*L2E);
            eb.x = exp2f(b.x*L2E); eb.y = exp2f(b.y*L2E);
            eb.z = exp2f(b.z*L2E); eb.w = exp2f(b.w*L2E);
            float4* rb = reinterpret_cast<float4*>(ring + ((t & (RINGD-1)) << 8));
            rb[lane]      = ea;
            rb[lane + 32] = eb;
            __syncwarp();
            if (lane == 0) {
                unsigned ca = (unsigned)__cvta_generic_to_shared(&cnt[t >> 3]);
                asm volatile("red.release.cta.shared::cta.add.u32 [%0], %1;"
                             :: "r"(ca), "r"(1) : "memory");
            }
            float s = ea.x + ea.y + ea.z + ea.w + eb.x + eb.y + eb.z + eb.w;
            #pragma unroll
            for (int o = 16; o; o >>= 1) s += __shfl_xor_sync(0xffffffffu, s, o);
            // exact product-exponent accumulation (log deferred to end)
            prod *= s;
            int bts = __float_as_int(prod);
            eacc += ((bts >> 23) & 255) - 127;
            prod = __int_as_float((bts & 0x807FFFFF) | 0x3F800000);
            a = an; b = bn;
        }
        if (lane == 0)
            wsum[wid] = __logf(prod) + (float)eacc * 0.69314718055994531f;
    }
    __syncthreads();

    if (tid == 0) {
        float slz = 0.0f;
        #pragma unroll
        for (int w = 0; w < 31; w++) slz += wsum[w];
        int tl = 0;
        for (int i = 0; i < L_; i++) tl += (stg[i] != 0);
        const int sa = 2 * tl, sb = 2 * tl - 1;
        float va = finm[sa], vb = finm[sb];
        int ea = fine_[min(sa >> 3, 31)];
        int eb = fine_[min(sb >> 3, 31)];
        int E  = max(ea, eb);
        float fa2 = __int_as_float(max(ea - E + 127, 0) << 23);
        float fb2 = __int_as_float(max(eb - E + 127, 0) << 23);
        float v = va * fa2 + vb * fb2;
        float loss = 0.0f;
        if (v > 0.0f && E > NEGH / 2) {
            float fin = logf(v) + (float)E * 0.69314718055994531f - slz;
            if (fin >= -1e29f) loss = -fin;
        }
        g_loss[n] = loss / (float)(tl > 0 ? tl : 1);

        __threadfence();
        int old = atomicAdd(&g_ctr, 1);
        if (old == N_ - 1) {
            float ssum = 0.0f;
            #pragma unroll 8
            for (int i = 0; i < N_; i++) ssum += g_loss[i];
            out[0] = ssum / (float)N_;
            g_ctr = 0;
            __threadfence();
        }
    }
}

// ---------------------------------------------------------------------------
extern "C" void kernel_launch(void* const* d_in, const int* in_sizes, int n_in,
                              void* d_out, int out_size) {
    const float* preds   = (const float*)d_in[0];
    const int*   targets = (const int*)d_in[1];

    ctc_all<<<N_, 1024>>>(preds, targets, (float*)d_out);
}

// round 11
// speedup vs baseline: 1.0753x; 1.0753x over previous
#include <cuda_runtime.h>
#include <math.h>

#define N_ 128
#define T_ 1024
#define C_ 256
#define L_ 128
#define NEGH (-(1 << 26))
#define RINGD 32             // ring depth in rows
#define FSTR 132             // feed row stride (floats): 128 labels + blank + pad

__device__ float g_loss[N_];
__device__ int   g_ctr;      // cross-CTA completion counter (self-resetting)

// ---------------------------------------------------------------------------
// One 1024-thread CTA per sample.  preds read ONCE.
//  24 producer warps: LDG row -> exp2f x8 -> STS full row (ring) -> syncwarp
//    -> gather label-ordered emissions into compact feed[slot][132] -> release
//    chunk counter -> logsumexp via product-exponent accumulator.
//  warp 31 (alone on SMSP3): CTC DP, 8 states/lane in registers.  Per step:
//    1 LDS.128 (4 odd-state emissions, conflict-free) + 1 broadcast LDS (blank)
//    + ~22 FLOPs; SHFL of new m7 issued at end of step (latency hidden).
//    One acquire-poll per 8 steps; watermark published per 8 steps.
//  Last CTA reduces g_loss -> out[0].
// ---------------------------------------------------------------------------
__global__ void __launch_bounds__(1024, 1) ctc_all(const float* __restrict__ preds,
                                                   const int*   __restrict__ targets,
                                                   float*       __restrict__ out) {
    const int n    = blockIdx.x;
    const int tid  = threadIdx.x;
    const int wid  = tid >> 5;
    const int lane = tid & 31;

    __shared__ __align__(16) float ring[RINGD * C_];   // full exp'd rows (32KB)
    __shared__ __align__(16) float feed[RINGD * FSTR]; // label-gathered rows (~17KB)
    __shared__ int   cnt[T_ / 8];
    __shared__ int   stg[L_];
    __shared__ float wsum[32];
    __shared__ float finm[260];
    __shared__ int   fine_[32];
    __shared__ volatile int s_prog;

    const float* P = preds + (size_t)n * T_ * C_;
    const float L2E = 1.4426950408889634f;

    if (tid < L_) stg[tid] = targets[n * L_ + tid];
    if (tid < T_ / 8) cnt[tid] = 0;
    if (tid < 32) wsum[tid] = 0.0f;
    if (tid == 0) s_prog = -8;
    __syncthreads();

    const unsigned cntb = (unsigned)__cvta_generic_to_shared(cnt);

    if (wid == 31) {
        // =================== DP warp ===================
        const int lab0 = stg[4*lane],   lab1 = stg[4*lane+1];
        const int lab2 = stg[4*lane+2], lab3 = stg[4*lane+3];
        const float sk1 = (lane == 0) ? 1.0f : ((lab0 != stg[4*lane-1]) ? 1.0f : 0.0f);
        const float sk3 = (lab1 != lab0) ? 1.0f : 0.0f;
        const float sk5 = (lab2 != lab1) ? 1.0f : 0.0f;
        const float sk7 = (lab3 != lab2) ? 1.0f : 0.0f;

        #define WAITCNT(K)                                                     \
        {   int cc_; unsigned ca_ = cntb + 4u * (unsigned)(K);                 \
            do { asm volatile("ld.acquire.cta.shared::cta.b32 %0, [%1];"       \
                              : "=r"(cc_) : "r"(ca_) : "memory");              \
            } while (cc_ < 8); }

        float m0=0,m1=0,m2=0,m3=0,m4=0,m5=0,m6=0,m7=0,m8=0;
        float m7n = 0.0f;
        int   el = 0;
        WAITCNT(0)                              // rows 0..7 resident
        if (lane == 0) { m0 = ring[0]; m1 = ring[lab0]; }   // alpha at t=0
        float fA = (lane == 0) ? 0.0f : 1.0f, fB = 1.0f;

        // 2-deep staging from feed: e = row1, n = row2; fw -> row3
        const float4* fd1 = reinterpret_cast<const float4*>(feed + 1 * FSTR);
        const float4* fd2 = reinterpret_cast<const float4*>(feed + 2 * FSTR);
        float4 q1 = fd1[lane], q2 = fd2[lane];
        float e0 = q1.x, e1 = q1.y, e2 = q1.z, e3 = q1.w, eB = feed[1*FSTR+128];
        float n0 = q2.x, n1 = q2.y, n2 = q2.z, n3 = q2.w, nB = feed[2*FSTR+128];
        int fw = 3 * FSTR;                      // word offset of row 3's feed

        #define STEPD(DO_STAGE)                                                \
        {                                                                      \
            float l0=0,l1=0,l2=0,l3=0,lB=0;                                    \
            if (DO_STAGE) {                                                    \
                const float4* fdp = reinterpret_cast<const float4*>(feed + fw);\
                float4 ql = fdp[lane];                                         \
                l0 = ql.x; l1 = ql.y; l2 = ql.z; l3 = ql.w;                    \
                lB = feed[fw + 128];                                           \
                fw += FSTR; fw = (fw == RINGD * FSTR) ? 0 : fw;                \
            }                                                                  \
            float in1 = (m7n * fA) * fB;                                       \
            m8 = (m8 + m7) * eB;                                               \
            m7 = fmaf(sk7, m5, m7 + m6) * e3;                                  \
            m6 = (m6 + m5) * eB;                                               \
            m5 = fmaf(sk5, m3, m5 + m4) * e2;                                  \
            m4 = (m4 + m3) * eB;                                               \
            m3 = fmaf(sk3, m1, m3 + m2) * e1;                                  \
            m2 = (m2 + m1) * eB;                                               \
            m1 = fmaf(sk1, in1, m1 + m0) * e0;                                 \
            m0 = (m0 + in1) * eB;                                              \
            m7n = __shfl_up_sync(0xffffffffu, m7, 1);   /* for next step */    \
            eB = nB; e0 = n0; e1 = n1; e2 = n2; e3 = n3;                       \
            nB = lB; n0 = l0; n1 = l1; n2 = l2; n3 = l3;                       \
        }

        #define RENORM                                                         \
        {                                                                      \
            float lm = fmaxf(fmaxf(fmaxf(m0,m1),fmaxf(m2,m3)),                 \
                             fmaxf(fmaxf(m4,m5),fmaxf(m6,m7)));                \
            lm = fmaxf(lm, m8);                                                \
            int bts = __float_as_int(lm);                                      \
            int x   = ((bts >> 23) & 255) - 127;                               \
            int elo = (lm > 0.0f) ? (el + x) : NEGH;                           \
            int eln = __shfl_up_sync(0xffffffffu, elo, 1);                     \
            if (lane == 0) eln = NEGH;                                         \
            int elf = max(elo, eln - 40);                                      \
            int elnf = __shfl_up_sync(0xffffffffu, elf, 1);                    \
            if (lane == 0) elnf = NEGH;                                        \
            int jmp = elf - el;                                                \
            int jc  = min(max(127 - jmp, 0), 254);                             \
            float sc = __int_as_float(jc << 23);                               \
            m0*=sc; m1*=sc; m2*=sc; m3*=sc; m4*=sc;                            \
            m5*=sc; m6*=sc; m7*=sc; m8*=sc;                                    \
            el = elf;                                                          \
            int d  = min(elnf - elf, 40);                                      \
            int h1 = d >> 1;                                                   \
            int h2 = d - h1;                                                   \
            fA = __int_as_float(max(h1 + 127, 0) << 23);                       \
            fB = __int_as_float(max(h2 + 127, 0) << 23);                       \
            if (lane == 0) fA = 0.0f;                                          \
            m7n = __shfl_up_sync(0xffffffffu, m7, 1);   /* rescaled re-shfl */ \
        }

        // blocks j=0..126: steps 8j+1..8j+8 (stage feed rows up to 8j+10)
        for (int j = 0; j < 127; j++) {
            WAITCNT(j + 1)                      // rows <= 8j+15 resident
            STEPD(1) STEPD(1) STEPD(1) STEPD(1)
            STEPD(1) STEPD(1) STEPD(1) STEPD(1)
            RENORM
            if (lane == 0) s_prog = 8 * j + 8;
        }
        // tail: steps 1017..1023 (stage rows 1019..1023, then none)
        STEPD(1) STEPD(1) STEPD(1) STEPD(1) STEPD(1) STEPD(0) STEPD(0)
        #undef STEPD
        #undef RENORM
        #undef WAITCNT

        finm[8*lane+0]=m0; finm[8*lane+1]=m1; finm[8*lane+2]=m2; finm[8*lane+3]=m3;
        finm[8*lane+4]=m4; finm[8*lane+5]=m5; finm[8*lane+6]=m6; finm[8*lane+7]=m7;
        if (lane == 31) finm[256] = m8;
        fine_[lane] = el;
    } else if ((wid & 3) != 3) {
        // =================== producer warps (24) ===================
        const int widx = (wid >> 2) * 3 + (wid & 3);   // 0..23
        const int lab0 = stg[4*lane],   lab1 = stg[4*lane+1];
        const int lab2 = stg[4*lane+2], lab3 = stg[4*lane+3];
        float prod = 1.0f;
        int   eacc = 0;
        for (int t = widx; t < T_; t += 24) {
            while (t - s_prog > 32) __nanosleep(64);   // ring back-pressure
            const float4* row = reinterpret_cast<const float4*>(P + (size_t)t * C_);
            float4 a = row[lane];
            float4 b = row[lane + 32];
            float4 ea, eb;
            ea.x = exp2f(a.x*L2E); ea.y = exp2f(a.y*L2E);
            ea.z = exp2f(a.z*L2E); ea.w = exp2f(a.w*L2E);
            eb.x = exp2f(b.x*L2E); eb.y = exp2f(b.y*L2E);
            eb.z = exp2f(b.z*L2E); eb.w = exp2f(b.w*L2E);
            const int rbw = (t & (RINGD-1)) << 8;
            float4* rb = reinterpret_cast<float4*>(ring + rbw);
            rb[lane]      = ea;
            rb[lane + 32] = eb;
            __syncwarp();
            // gather label-ordered emissions into the compact feed row
            float g0 = ring[rbw + lab0], g1 = ring[rbw + lab1];
            float g2 = ring[rbw + lab2], g3 = ring[rbw + lab3];
            const int fwp = (t & (RINGD-1)) * FSTR;
            reinterpret_cast<float4*>(feed + fwp)[lane] = make_float4(g0, g1, g2, g3);
            if (lane == 31) feed[fwp + 128] = ring[rbw];   // blank emission
            __syncwarp();
            if (lane == 0) {
                unsigned ca = (unsigned)__cvta_generic_to_shared(&cnt[t >> 3]);
                asm volatile("red.release.cta.shared::cta.add.u32 [%0], %1;"
                             :: "r"(ca), "r"(1) : "memory");
            }
            // logsumexp: exact product-exponent accumulation
            float s = ea.x + ea.y + ea.z + ea.w + eb.x + eb.y + eb.z + eb.w;
            #pragma unroll
            for (int o = 16; o; o >>= 1) s += __shfl_xor_sync(0xffffffffu, s, o);
            prod *= s;
            int bts = __float_as_int(prod);
            eacc += ((bts >> 23) & 255) - 127;
            prod = __int_as_float((bts & 0x807FFFFF) | 0x3F800000);
        }
        if (lane == 0)
            wsum[wid] = __logf(prod) + (float)eacc * 0.69314718055994531f;
    }
    __syncthreads();

    if (tid == 0) {
        float slz = 0.0f;
        #pragma unroll
        for (int w = 0; w < 31; w++) slz += wsum[w];
        int tl = 0;
        for (int i = 0; i < L_; i++) tl += (stg[i] != 0);
        const int sa = 2 * tl, sb = 2 * tl - 1;
        float va = finm[sa], vb = finm[sb];
        int ea = fine_[min(sa >> 3, 31)];
        int eb = fine_[min(sb >> 3, 31)];
        int E  = max(ea, eb);
        float fa2 = __int_as_float(max(ea - E + 127, 0) << 23);
        float fb2 = __int_as_float(max(eb - E + 127, 0) << 23);
        float v = va * fa2 + vb * fb2;
        float loss = 0.0f;
        if (v > 0.0f && E > NEGH / 2) {
            float fin = logf(v) + (float)E * 0.69314718055994531f - slz;
            if (fin >= -1e29f) loss = -fin;
        }
        g_loss[n] = loss / (float)(tl > 0 ? tl : 1);

        __threadfence();
        int old = atomicAdd(&g_ctr, 1);
        if (old == N_ - 1) {
            float ssum = 0.0f;
            #pragma unroll 8
            for (int i = 0; i < N_; i++) ssum += g_loss[i];
            out[0] = ssum / (float)N_;
            g_ctr = 0;
            __threadfence();
        }
    }
}

// ---------------------------------------------------------------------------
extern "C" void kernel_launch(void* const* d_in, const int* in_sizes, int n_in,
                              void* d_out, int out_size) {
    const float* preds   = (const float*)d_in[0];
    const int*   targets = (const int*)d_in[1];

    ctc_all<<<N_, 1024>>>(preds, targets, (float*)d_out);
}